// round 6
// baseline (speedup 1.0000x reference)
#include <cuda_runtime.h>
#include <cuda_bf16.h>
#include <cstdint>

#define N_NODES 100000
#define N_EDGES 1600000
#define HID 128

// ---------------- scratch (device globals; no allocation) ----------------
__device__ float g_cnt [N_NODES];
__device__ float g_agg1[N_NODES * 6];
__device__ float g_h1  [N_NODES * HID];
__device__ float g_agg2[N_NODES * HID];
__device__ float g_h2  [N_NODES * HID];
__device__ float g_p   [N_NODES * HID];   // h2 @ W_e1[0:128]
__device__ float g_q   [N_NODES * HID];   // h2 @ W_e1[128:256]

// ---------------- packed fp32x2 helpers ----------------
__device__ __forceinline__ void fma2(unsigned long long& acc,
                                     unsigned long long a, unsigned long long b) {
    asm("fma.rn.f32x2 %0, %1, %2, %0;" : "+l"(acc) : "l"(a), "l"(b));
}
__device__ __forceinline__ unsigned long long dup2(float x) {
    unsigned long long r;
    unsigned int u = __float_as_uint(x);
    asm("mov.b64 %0, {%1, %1};" : "=l"(r) : "r"(u));
    return r;
}
__device__ __forceinline__ float2 unpk2(unsigned long long v) {
    float2 f;
    asm("mov.b64 {%0, %1}, %2;" : "=f"(f.x), "=f"(f.y) : "l"(v));
    return f;
}

// ---------------- warp MMA helpers (baseline PTX, no arch-specific feats) ----
__device__ __forceinline__ uint32_t smem_u32(const void* p) {
    uint32_t a;
    asm("{ .reg .u64 t; cvta.to.shared.u64 t, %1; cvt.u32.u64 %0, t; }" : "=r"(a) : "l"(p));
    return a;
}
__device__ __forceinline__ void mma16816(float* d, const uint32_t* a, const uint32_t* b) {
    asm volatile(
        "mma.sync.aligned.m16n8k16.row.col.f32.bf16.bf16.f32 "
        "{%0,%1,%2,%3}, {%4,%5,%6,%7}, {%8,%9}, {%0,%1,%2,%3};"
        : "+f"(d[0]), "+f"(d[1]), "+f"(d[2]), "+f"(d[3])
        : "r"(a[0]), "r"(a[1]), "r"(a[2]), "r"(a[3]), "r"(b[0]), "r"(b[1]));
}
__device__ __forceinline__ void ldsm4(uint32_t* r, uint32_t addr) {
    asm volatile("ldmatrix.sync.aligned.m8n8.x4.shared.b16 {%0,%1,%2,%3}, [%4];"
                 : "=r"(r[0]), "=r"(r[1]), "=r"(r[2]), "=r"(r[3]) : "r"(addr));
}
__device__ __forceinline__ uint32_t pack_bf16(float x, float y) {
    __nv_bfloat16 bx = __float2bfloat16(x), by = __float2bfloat16(y);
    return ((uint32_t)__bfloat16_as_ushort(by) << 16) | __bfloat16_as_ushort(bx);
}

// ---------------- zero scratch accumulators ----------------
__global__ void k_zero() {
    int i = blockIdx.x * 256 + threadIdx.x;
    float4 z = make_float4(0.f, 0.f, 0.f, 0.f);
    if (i < N_NODES * HID / 4) reinterpret_cast<float4*>(g_agg2)[i] = z;
    if (i < N_NODES * 6 / 4)   reinterpret_cast<float4*>(g_agg1)[i] = z;
    if (i < N_NODES / 4)       reinterpret_cast<float4*>(g_cnt)[i]  = z;
}

// ---------------- SAGE layer 1 scatter ----------------
__global__ void k_agg1(const float* __restrict__ x, const int* __restrict__ ei) {
    int e = blockIdx.x * 256 + threadIdx.x;
    int s = ei[e];
    int d = ei[N_EDGES + e];
    atomicAdd(&g_cnt[d], 1.0f);
    const float2* xr = reinterpret_cast<const float2*>(x + s * 6);
    float* dst = &g_agg1[d * 6];
#pragma unroll
    for (int k = 0; k < 3; k++) {
        float2 v = xr[k];
        asm volatile("red.global.add.v2.f32 [%0], {%1, %2};"
                     :: "l"(dst + k * 2), "f"(v.x), "f"(v.y) : "memory");
    }
}

// ---------------- h1 = relu(x@W1r + mean1@W1n + b1) ----------------
__global__ void k_h1(const float* __restrict__ x,
                     const float* __restrict__ w1r, const float* __restrict__ w1n,
                     const float* __restrict__ b1) {
    int t = threadIdx.x;
    int node = blockIdx.x * 2 + (t >> 7);
    int j = t & 127;
    float inv = 1.0f / fmaxf(g_cnt[node], 1.0f);
    float acc = b1[j];
#pragma unroll
    for (int k = 0; k < 6; k++) {
        acc += x[node * 6 + k] * w1r[k * 128 + j]
             + g_agg1[node * 6 + k] * inv * w1n[k * 128 + j];
    }
    g_h1[node * 128 + j] = fmaxf(acc, 0.f);
}

// ---------------- scatter h1[src] into agg2 (vector red) ----------------
__global__ void k_agg2(const int* __restrict__ ei) {
    int w = blockIdx.x * 8 + (threadIdx.x >> 5);
    int lane = threadIdx.x & 31;
    int s = ei[w];
    int d = ei[N_EDGES + w];
    float4 v = *reinterpret_cast<const float4*>(&g_h1[s * 128 + lane * 4]);
    float* dst = &g_agg2[d * 128 + lane * 4];
    asm volatile("red.global.add.v4.f32 [%0], {%1, %2, %3, %4};"
                 :: "l"(dst), "f"(v.x), "f"(v.y), "f"(v.z), "f"(v.w) : "memory");
}

// ---------------- h2 = relu(h1@W2r + mean2@W2n + b2), dual-A GEMM ----------------
__global__ void k_h2(const float* __restrict__ W1, const float* __restrict__ W2,
                     const float* __restrict__ bias) {
    __shared__ __align__(16) float As1[16][64];
    __shared__ __align__(16) float As2[16][64];
    __shared__ __align__(16) float Bs1[16][64];
    __shared__ __align__(16) float Bs2[16][64];
    int t = threadIdx.x;
    int row0 = blockIdx.x * 64;
    int col0 = blockIdx.y * 64;
    int lnode = t >> 2;
    int lk4   = (t & 3) * 4;
    int lkB   = t >> 4;
    int ljB   = (t & 15) * 4;
    int tx = t & 15, ty = t >> 4;
    unsigned long long acc[4][2] = {};

    for (int k0 = 0; k0 < 128; k0 += 16) {
        int row = row0 + lnode;
        float4 a1, a2;
        if (row < N_NODES) {
            a1 = *reinterpret_cast<const float4*>(&g_h1[row * 128 + k0 + lk4]);
            a2 = *reinterpret_cast<const float4*>(&g_agg2[row * 128 + k0 + lk4]);
            float inv = 1.0f / fmaxf(g_cnt[row], 1.0f);
            a2.x *= inv; a2.y *= inv; a2.z *= inv; a2.w *= inv;
        } else {
            a1 = a2 = make_float4(0.f, 0.f, 0.f, 0.f);
        }
        As1[lk4 + 0][lnode] = a1.x; As1[lk4 + 1][lnode] = a1.y;
        As1[lk4 + 2][lnode] = a1.z; As1[lk4 + 3][lnode] = a1.w;
        As2[lk4 + 0][lnode] = a2.x; As2[lk4 + 1][lnode] = a2.y;
        As2[lk4 + 2][lnode] = a2.z; As2[lk4 + 3][lnode] = a2.w;
        *reinterpret_cast<float4*>(&Bs1[lkB][ljB]) =
            *reinterpret_cast<const float4*>(&W1[(k0 + lkB) * 128 + col0 + ljB]);
        *reinterpret_cast<float4*>(&Bs2[lkB][ljB]) =
            *reinterpret_cast<const float4*>(&W2[(k0 + lkB) * 128 + col0 + ljB]);
        __syncthreads();
#pragma unroll
        for (int kk = 0; kk < 16; kk++) {
            float4 a1v = *reinterpret_cast<float4*>(&As1[kk][ty * 4]);
            float4 a2v = *reinterpret_cast<float4*>(&As2[kk][ty * 4]);
            ulonglong2 b1v = *reinterpret_cast<ulonglong2*>(&Bs1[kk][tx * 4]);
            ulonglong2 b2v = *reinterpret_cast<ulonglong2*>(&Bs2[kk][tx * 4]);
            unsigned long long a1d[4] = {dup2(a1v.x), dup2(a1v.y), dup2(a1v.z), dup2(a1v.w)};
            unsigned long long a2d[4] = {dup2(a2v.x), dup2(a2v.y), dup2(a2v.z), dup2(a2v.w)};
#pragma unroll
            for (int i = 0; i < 4; i++) {
                fma2(acc[i][0], a1d[i], b1v.x);
                fma2(acc[i][0], a2d[i], b2v.x);
                fma2(acc[i][1], a1d[i], b1v.y);
                fma2(acc[i][1], a2d[i], b2v.y);
            }
        }
        __syncthreads();
    }

    int row = row0 + ty * 4;
    int col = col0 + tx * 4;
#pragma unroll
    for (int i = 0; i < 4; i++) {
        if (row + i < N_NODES) {
            float2 lo = unpk2(acc[i][0]);
            float2 hi = unpk2(acc[i][1]);
            float4 c;
            c.x = fmaxf(lo.x + bias[col + 0], 0.f);
            c.y = fmaxf(lo.y + bias[col + 1], 0.f);
            c.z = fmaxf(hi.x + bias[col + 2], 0.f);
            c.w = fmaxf(hi.y + bias[col + 3], 0.f);
            *reinterpret_cast<float4*>(&g_h2[(row + i) * 128 + col]) = c;
        }
    }
}

// ---------------- p = h2@W_a, q = h2@W_b ----------------
__global__ void k_pq(const float* __restrict__ we1) {
    __shared__ __align__(16) float As[16][64];
    __shared__ __align__(16) float Bs1[16][64];
    __shared__ __align__(16) float Bs2[16][64];
    int t = threadIdx.x;
    int row0 = blockIdx.x * 64;
    int col0 = blockIdx.y * 64;
    int lnode = t >> 2;
    int lk4   = (t & 3) * 4;
    int lkB   = t >> 4;
    int ljB   = (t & 15) * 4;
    int tx = t & 15, ty = t >> 4;
    unsigned long long acc1[4][2] = {};
    unsigned long long acc2[4][2] = {};

    for (int k0 = 0; k0 < 128; k0 += 16) {
        int row = row0 + lnode;
        float4 a;
        if (row < N_NODES)
            a = *reinterpret_cast<const float4*>(&g_h2[row * 128 + k0 + lk4]);
        else
            a = make_float4(0.f, 0.f, 0.f, 0.f);
        As[lk4 + 0][lnode] = a.x; As[lk4 + 1][lnode] = a.y;
        As[lk4 + 2][lnode] = a.z; As[lk4 + 3][lnode] = a.w;
        *reinterpret_cast<float4*>(&Bs1[lkB][ljB]) =
            *reinterpret_cast<const float4*>(&we1[(k0 + lkB) * 128 + col0 + ljB]);
        *reinterpret_cast<float4*>(&Bs2[lkB][ljB]) =
            *reinterpret_cast<const float4*>(&we1[(128 + k0 + lkB) * 128 + col0 + ljB]);
        __syncthreads();
#pragma unroll
        for (int kk = 0; kk < 16; kk++) {
            float4 av  = *reinterpret_cast<float4*>(&As[kk][ty * 4]);
            ulonglong2 b1v = *reinterpret_cast<ulonglong2*>(&Bs1[kk][tx * 4]);
            ulonglong2 b2v = *reinterpret_cast<ulonglong2*>(&Bs2[kk][tx * 4]);
            unsigned long long ad[4] = {dup2(av.x), dup2(av.y), dup2(av.z), dup2(av.w)};
#pragma unroll
            for (int i = 0; i < 4; i++) {
                fma2(acc1[i][0], ad[i], b1v.x);
                fma2(acc1[i][1], ad[i], b1v.y);
                fma2(acc2[i][0], ad[i], b2v.x);
                fma2(acc2[i][1], ad[i], b2v.y);
            }
        }
        __syncthreads();
    }

    int row = row0 + ty * 4;
    int col = col0 + tx * 4;
#pragma unroll
    for (int i = 0; i < 4; i++) {
        if (row + i < N_NODES) {
            float2 p0 = unpk2(acc1[i][0]), p1 = unpk2(acc1[i][1]);
            float2 q0 = unpk2(acc2[i][0]), q1 = unpk2(acc2[i][1]);
            *reinterpret_cast<float4*>(&g_p[(row + i) * 128 + col]) =
                make_float4(p0.x, p0.y, p1.x, p1.y);
            *reinterpret_cast<float4*>(&g_q[(row + i) * 128 + col]) =
                make_float4(q0.x, q0.y, q1.x, q1.y);
        }
    }
}

// ================= edge MLP via warp HMMA (bf16 2-term split) =================
// Per 128-edge tile: e1 = relu(p[src]+q[dst]+ea@Wc+b1), split into bf16 hi/lo,
// staged in smem (136-elem padded rows). W2 split bf16 lives in registers.
// D[128x64] = Ahi*Bhi + Ahi*Blo + Alo*Bhi via mma.sync m16n8k16, fp32 acc.
// Epilogue: out = sum_c relu(D+b2)*w3 + b3.
#define AROW 136                      // padded row (bf16 elems); 272B, 16B-mult
#define SM_A_HI   0                   // 128*272 = 34816 B
#define SM_A_LO   34816               // 34816 B
#define SM_OUTACC 69632               // float[128]
#define SM_B1S    70144               // float[128]
#define SM_WCS    70656               // float[512]
#define SM_B2S    72704               // float[64]
#define SM_W3S    72960               // float[64]
#define SM_EAS    73216               // float[512]
#define SM_SRC    75264               // int[128]
#define SM_DST    75776               // int[128]
#define SM_EDGE_TOTAL 76288

#define N_TILES (N_EDGES / 128)

__global__ __launch_bounds__(256, 1)
void k_edge_mma(const int* __restrict__ ei, const float* __restrict__ ea,
                const float* __restrict__ we1, const float* __restrict__ be1,
                const float* __restrict__ we2, const float* __restrict__ be2,
                const float* __restrict__ we3, const float* __restrict__ be3,
                float* __restrict__ out) {
    extern __shared__ __align__(16) char smem[];
    uint32_t smem_base = smem_u32(smem);
    int t = threadIdx.x;
    int wid = t >> 5, lane = t & 31;
    int wm = wid >> 1;            // warp M tile: rows wm*32..+31
    int wn = wid & 1;             // warp N half: cols wn*32..+31

    float* out_acc = (float*)(smem + SM_OUTACC);
    float* b1s = (float*)(smem + SM_B1S);
    float* wcs = (float*)(smem + SM_WCS);
    float* b2s = (float*)(smem + SM_B2S);
    float* w3s = (float*)(smem + SM_W3S);
    float* eas = (float*)(smem + SM_EAS);
    int*   srcs = (int*)(smem + SM_SRC);
    int*   dsts = (int*)(smem + SM_DST);

    if (t < 128) b1s[t] = be1[t];
    for (int i = t; i < 512; i += 256) wcs[i] = we1[256 * 128 + i];
    if (t < 64) { b2s[t] = be2[t]; w3s[t] = we3[t]; }

    // ---- load W2 hi/lo fragments into registers (once per block) ----
    // frag [kk][nn]: n = wn*32 + nn*8 + lane/4 ; k = kk*16 + (lane%4)*2
    uint32_t bhi[8][4][2], blo[8][4][2];
    {
        int n = wn * 32 + (lane >> 2);
        int kb = (lane & 3) * 2;
#pragma unroll
        for (int kk = 0; kk < 8; kk++) {
#pragma unroll
            for (int nn = 0; nn < 4; nn++) {
                int nc = n + nn * 8;
                int k0 = kk * 16 + kb;
                float w00 = we2[k0 * 64 + nc];
                float w01 = we2[(k0 + 1) * 64 + nc];
                float w10 = we2[(k0 + 8) * 64 + nc];
                float w11 = we2[(k0 + 9) * 64 + nc];
                float h00 = __bfloat162float(__float2bfloat16(w00));
                float h01 = __bfloat162float(__float2bfloat16(w01));
                float h10 = __bfloat162float(__float2bfloat16(w10));
                float h11 = __bfloat162float(__float2bfloat16(w11));
                bhi[kk][nn][0] = pack_bf16(h00, h01);
                bhi[kk][nn][1] = pack_bf16(h10, h11);
                blo[kk][nn][0] = pack_bf16(w00 - h00, w01 - h01);
                blo[kk][nn][1] = pack_bf16(w10 - h10, w11 - h11);
            }
        }
    }
    float be3v = be3[0];

    // ldmatrix per-thread source row/col within a 16x16 A tile
    int lrow = (lane & 7) + ((lane & 8) ? 8 : 0);
    int lcol = (lane & 16) ? 8 : 0;
    __syncthreads();

    for (int tile = blockIdx.x; tile < N_TILES; tile += gridDim.x) {
        int e0 = tile * 128;
        if (t < 128) { srcs[t] = ei[e0 + t]; out_acc[t] = 0.f; }
        else         { dsts[t - 128] = ei[N_EDGES + e0 + (t - 128)]; }
        for (int i = t; i < 512; i += 256) eas[i] = ea[e0 * 4 + i];
        __syncthreads();

        // ---- gather + e1 + bf16 split into padded smem A ----
#pragma unroll 4
        for (int i = 0; i < 32; i++) {
            int u = i * 256 + t;
            int edge = u >> 6;
            int k = (u & 63) * 2;
            int s = srcs[edge], d = dsts[edge];
            float2 pv = *reinterpret_cast<const float2*>(&g_p[s * 128 + k]);
            float2 qv = *reinterpret_cast<const float2*>(&g_q[d * 128 + k]);
            const float* eap = &eas[edge * 4];
            float v0 = pv.x + qv.x + b1s[k]
                     + eap[0] * wcs[k]       + eap[1] * wcs[128 + k]
                     + eap[2] * wcs[256 + k] + eap[3] * wcs[384 + k];
            float v1 = pv.y + qv.y + b1s[k + 1]
                     + eap[0] * wcs[k + 1]   + eap[1] * wcs[129 + k]
                     + eap[2] * wcs[257 + k] + eap[3] * wcs[385 + k];
            v0 = fmaxf(v0, 0.f);
            v1 = fmaxf(v1, 0.f);
            float h0 = __bfloat162float(__float2bfloat16(v0));
            float h1 = __bfloat162float(__float2bfloat16(v1));
            uint32_t off = (uint32_t)edge * (AROW * 2) + (uint32_t)k * 2;
            *(uint32_t*)(smem + SM_A_HI + off) = pack_bf16(h0, h1);
            *(uint32_t*)(smem + SM_A_LO + off) = pack_bf16(v0 - h0, v1 - h1);
        }
        __syncthreads();

        // ---- HMMA mainloop: warp tile 32(M)x32(N), K=128 ----
        float acc[2][4][4];
#pragma unroll
        for (int mi = 0; mi < 2; mi++)
#pragma unroll
            for (int nn = 0; nn < 4; nn++)
#pragma unroll
                for (int r = 0; r < 4; r++) acc[mi][nn][r] = 0.f;

#pragma unroll
        for (int kk = 0; kk < 8; kk++) {
            uint32_t ahi[2][4], alo[2][4];
#pragma unroll
            for (int mi = 0; mi < 2; mi++) {
                uint32_t boff = (uint32_t)(wm * 32 + mi * 16 + lrow) * (AROW * 2)
                              + (uint32_t)(kk * 16 + lcol) * 2;
                ldsm4(ahi[mi], smem_base + SM_A_HI + boff);
                ldsm4(alo[mi], smem_base + SM_A_LO + boff);
            }
#pragma unroll
            for (int mi = 0; mi < 2; mi++) {
#pragma unroll
                for (int nn = 0; nn < 4; nn++) {
                    mma16816(acc[mi][nn], ahi[mi], bhi[kk][nn]);
                    mma16816(acc[mi][nn], ahi[mi], blo[kk][nn]);
                    mma16816(acc[mi][nn], alo[mi], bhi[kk][nn]);
                }
            }
        }

        // ---- epilogue: relu(D+b2)*w3, reduce over N ----
        float part[2][2] = {{0.f, 0.f}, {0.f, 0.f}};
#pragma unroll
        for (int mi = 0; mi < 2; mi++) {
#pragma unroll
            for (int nn = 0; nn < 4; nn++) {
                int c0 = wn * 32 + nn * 8 + (lane & 3) * 2;
                float w30 = w3s[c0], w31 = w3s[c0 + 1];
                float bb0 = b2s[c0], bb1 = b2s[c0 + 1];
                part[mi][0] += fmaxf(acc[mi][nn][0] + bb0, 0.f) * w30
                             + fmaxf(acc[mi][nn][1] + bb1, 0.f) * w31;
                part[mi][1] += fmaxf(acc[mi][nn][2] + bb0, 0.f) * w30
                             + fmaxf(acc[mi][nn][3] + bb1, 0.f) * w31;
            }
        }
#pragma unroll
        for (int mi = 0; mi < 2; mi++) {
#pragma unroll
            for (int g = 0; g < 2; g++) {
                part[mi][g] += __shfl_xor_sync(0xffffffffu, part[mi][g], 1);
                part[mi][g] += __shfl_xor_sync(0xffffffffu, part[mi][g], 2);
            }
        }
        if ((lane & 3) == 0) {
            int row = wm * 32 + (lane >> 2);
            atomicAdd(&out_acc[row],      part[0][0]);
            atomicAdd(&out_acc[row + 8],  part[0][1]);
            atomicAdd(&out_acc[row + 16], part[1][0]);
            atomicAdd(&out_acc[row + 24], part[1][1]);
        }
        __syncthreads();
        if (t < 128) out[e0 + t] = out_acc[t] + be3v;
        __syncthreads();
    }
}

// ---------------- launch ----------------
extern "C" void kernel_launch(void* const* d_in, const int* in_sizes, int n_in,
                              void* d_out, int out_size) {
    const float* x   = (const float*)d_in[0];
    const int*   ei  = (const int*)d_in[1];
    const float* ea  = (const float*)d_in[2];
    const float* w1r = (const float*)d_in[3];
    const float* w1n = (const float*)d_in[4];
    const float* b1  = (const float*)d_in[5];
    const float* w2r = (const float*)d_in[6];
    const float* w2n = (const float*)d_in[7];
    const float* b2  = (const float*)d_in[8];
    const float* we1 = (const float*)d_in[9];
    const float* be1 = (const float*)d_in[10];
    const float* we2 = (const float*)d_in[11];
    const float* be2 = (const float*)d_in[12];
    const float* we3 = (const float*)d_in[13];
    const float* be3 = (const float*)d_in[14];
    float* out = (float*)d_out;

    cudaFuncSetAttribute(k_edge_mma, cudaFuncAttributeMaxDynamicSharedMemorySize,
                         SM_EDGE_TOTAL);

    k_zero<<<12500, 256>>>();
    k_agg1<<<N_EDGES / 256, 256>>>(x, ei);
    k_h1<<<N_NODES / 2, 256>>>(x, w1r, w1n, b1);
    k_agg2<<<N_EDGES / 8, 256>>>(ei);
    k_h2<<<dim3((N_NODES + 63) / 64, 2), 256>>>(w2r, w2n, b2);
    k_pq<<<dim3((N_NODES + 63) / 64, 2), 256>>>(we1);
    k_edge_mma<<<148, 256, SM_EDGE_TOTAL>>>(ei, ea, we1, be1, we2, be2, we3, be3, out);
}

// round 7
// speedup vs baseline: 1.7298x; 1.7298x over previous
#include <cuda_runtime.h>
#include <cuda_bf16.h>
#include <cstdint>

#define N_NODES 100000
#define N_EDGES 1600000
#define HID 128

// ---------------- scratch (device globals; no allocation) ----------------
__device__ float g_cnt [N_NODES];
__device__ float g_agg1[N_NODES * 6];
__device__ float g_h1  [N_NODES * HID];
__device__ float g_agg2[N_NODES * HID];
__device__ float g_h2  [N_NODES * HID];
__device__ float g_p   [N_NODES * HID];   // h2 @ W_e1[0:128]
__device__ float g_q   [N_NODES * HID];   // h2 @ W_e1[128:256]

// ---------------- packed fp32x2 helpers ----------------
__device__ __forceinline__ void fma2(unsigned long long& acc,
                                     unsigned long long a, unsigned long long b) {
    asm("fma.rn.f32x2 %0, %1, %2, %0;" : "+l"(acc) : "l"(a), "l"(b));
}
__device__ __forceinline__ unsigned long long dup2(float x) {
    unsigned long long r;
    unsigned int u = __float_as_uint(x);
    asm("mov.b64 %0, {%1, %1};" : "=l"(r) : "r"(u));
    return r;
}
__device__ __forceinline__ float2 unpk2(unsigned long long v) {
    float2 f;
    asm("mov.b64 {%0, %1}, %2;" : "=f"(f.x), "=f"(f.y) : "l"(v));
    return f;
}

// ---------------- warp MMA helpers (baseline PTX) ----------------
__device__ __forceinline__ uint32_t smem_u32(const void* p) {
    uint32_t a;
    asm("{ .reg .u64 t; cvta.to.shared.u64 t, %1; cvt.u32.u64 %0, t; }" : "=r"(a) : "l"(p));
    return a;
}
__device__ __forceinline__ void mma16816(float* d, const uint32_t* a, const uint32_t* b) {
    asm volatile(
        "mma.sync.aligned.m16n8k16.row.col.f32.bf16.bf16.f32 "
        "{%0,%1,%2,%3}, {%4,%5,%6,%7}, {%8,%9}, {%0,%1,%2,%3};"
        : "+f"(d[0]), "+f"(d[1]), "+f"(d[2]), "+f"(d[3])
        : "r"(a[0]), "r"(a[1]), "r"(a[2]), "r"(a[3]), "r"(b[0]), "r"(b[1]));
}
__device__ __forceinline__ void ldsm4(uint32_t* r, uint32_t addr) {
    asm volatile("ldmatrix.sync.aligned.m8n8.x4.shared.b16 {%0,%1,%2,%3}, [%4];"
                 : "=r"(r[0]), "=r"(r[1]), "=r"(r[2]), "=r"(r[3]) : "r"(addr));
}
__device__ __forceinline__ uint32_t pack_bf16(float x, float y) {
    __nv_bfloat16 bx = __float2bfloat16(x), by = __float2bfloat16(y);
    return ((uint32_t)__bfloat16_as_ushort(by) << 16) | __bfloat16_as_ushort(bx);
}

// ---------------- zero scratch accumulators ----------------
__global__ void k_zero() {
    int i = blockIdx.x * 256 + threadIdx.x;
    float4 z = make_float4(0.f, 0.f, 0.f, 0.f);
    if (i < N_NODES * HID / 4) reinterpret_cast<float4*>(g_agg2)[i] = z;
    if (i < N_NODES * 6 / 4)   reinterpret_cast<float4*>(g_agg1)[i] = z;
    if (i < N_NODES / 4)       reinterpret_cast<float4*>(g_cnt)[i]  = z;
}

// ---------------- SAGE layer 1 scatter ----------------
__global__ void k_agg1(const float* __restrict__ x, const int* __restrict__ ei) {
    int e = blockIdx.x * 256 + threadIdx.x;
    int s = ei[e];
    int d = ei[N_EDGES + e];
    atomicAdd(&g_cnt[d], 1.0f);
    const float2* xr = reinterpret_cast<const float2*>(x + s * 6);
    float* dst = &g_agg1[d * 6];
#pragma unroll
    for (int k = 0; k < 3; k++) {
        float2 v = xr[k];
        asm volatile("red.global.add.v2.f32 [%0], {%1, %2};"
                     :: "l"(dst + k * 2), "f"(v.x), "f"(v.y) : "memory");
    }
}

// ---------------- h1 = relu(x@W1r + mean1@W1n + b1) ----------------
__global__ void k_h1(const float* __restrict__ x,
                     const float* __restrict__ w1r, const float* __restrict__ w1n,
                     const float* __restrict__ b1) {
    int t = threadIdx.x;
    int node = blockIdx.x * 2 + (t >> 7);
    int j = t & 127;
    float inv = 1.0f / fmaxf(g_cnt[node], 1.0f);
    float acc = b1[j];
#pragma unroll
    for (int k = 0; k < 6; k++) {
        acc += x[node * 6 + k] * w1r[k * 128 + j]
             + g_agg1[node * 6 + k] * inv * w1n[k * 128 + j];
    }
    g_h1[node * 128 + j] = fmaxf(acc, 0.f);
}

// ---------------- scatter h1[src] into agg2 (vector red) ----------------
__global__ void k_agg2(const int* __restrict__ ei) {
    int w = blockIdx.x * 8 + (threadIdx.x >> 5);
    int lane = threadIdx.x & 31;
    int s = ei[w];
    int d = ei[N_EDGES + w];
    float4 v = *reinterpret_cast<const float4*>(&g_h1[s * 128 + lane * 4]);
    float* dst = &g_agg2[d * 128 + lane * 4];
    asm volatile("red.global.add.v4.f32 [%0], {%1, %2, %3, %4};"
                 :: "l"(dst), "f"(v.x), "f"(v.y), "f"(v.z), "f"(v.w) : "memory");
}

// ---------------- h2 = relu(h1@W2r + mean2@W2n + b2), dual-A GEMM ----------------
__global__ void k_h2(const float* __restrict__ W1, const float* __restrict__ W2,
                     const float* __restrict__ bias) {
    __shared__ __align__(16) float As1[16][64];
    __shared__ __align__(16) float As2[16][64];
    __shared__ __align__(16) float Bs1[16][64];
    __shared__ __align__(16) float Bs2[16][64];
    int t = threadIdx.x;
    int row0 = blockIdx.x * 64;
    int col0 = blockIdx.y * 64;
    int lnode = t >> 2;
    int lk4   = (t & 3) * 4;
    int lkB   = t >> 4;
    int ljB   = (t & 15) * 4;
    int tx = t & 15, ty = t >> 4;
    unsigned long long acc[4][2] = {};

    for (int k0 = 0; k0 < 128; k0 += 16) {
        int row = row0 + lnode;
        float4 a1, a2;
        if (row < N_NODES) {
            a1 = *reinterpret_cast<const float4*>(&g_h1[row * 128 + k0 + lk4]);
            a2 = *reinterpret_cast<const float4*>(&g_agg2[row * 128 + k0 + lk4]);
            float inv = 1.0f / fmaxf(g_cnt[row], 1.0f);
            a2.x *= inv; a2.y *= inv; a2.z *= inv; a2.w *= inv;
        } else {
            a1 = a2 = make_float4(0.f, 0.f, 0.f, 0.f);
        }
        As1[lk4 + 0][lnode] = a1.x; As1[lk4 + 1][lnode] = a1.y;
        As1[lk4 + 2][lnode] = a1.z; As1[lk4 + 3][lnode] = a1.w;
        As2[lk4 + 0][lnode] = a2.x; As2[lk4 + 1][lnode] = a2.y;
        As2[lk4 + 2][lnode] = a2.z; As2[lk4 + 3][lnode] = a2.w;
        *reinterpret_cast<float4*>(&Bs1[lkB][ljB]) =
            *reinterpret_cast<const float4*>(&W1[(k0 + lkB) * 128 + col0 + ljB]);
        *reinterpret_cast<float4*>(&Bs2[lkB][ljB]) =
            *reinterpret_cast<const float4*>(&W2[(k0 + lkB) * 128 + col0 + ljB]);
        __syncthreads();
#pragma unroll
        for (int kk = 0; kk < 16; kk++) {
            float4 a1v = *reinterpret_cast<float4*>(&As1[kk][ty * 4]);
            float4 a2v = *reinterpret_cast<float4*>(&As2[kk][ty * 4]);
            ulonglong2 b1v = *reinterpret_cast<ulonglong2*>(&Bs1[kk][tx * 4]);
            ulonglong2 b2v = *reinterpret_cast<ulonglong2*>(&Bs2[kk][tx * 4]);
            unsigned long long a1d[4] = {dup2(a1v.x), dup2(a1v.y), dup2(a1v.z), dup2(a1v.w)};
            unsigned long long a2d[4] = {dup2(a2v.x), dup2(a2v.y), dup2(a2v.z), dup2(a2v.w)};
#pragma unroll
            for (int i = 0; i < 4; i++) {
                fma2(acc[i][0], a1d[i], b1v.x);
                fma2(acc[i][0], a2d[i], b2v.x);
                fma2(acc[i][1], a1d[i], b1v.y);
                fma2(acc[i][1], a2d[i], b2v.y);
            }
        }
        __syncthreads();
    }

    int row = row0 + ty * 4;
    int col = col0 + tx * 4;
#pragma unroll
    for (int i = 0; i < 4; i++) {
        if (row + i < N_NODES) {
            float2 lo = unpk2(acc[i][0]);
            float2 hi = unpk2(acc[i][1]);
            float4 c;
            c.x = fmaxf(lo.x + bias[col + 0], 0.f);
            c.y = fmaxf(lo.y + bias[col + 1], 0.f);
            c.z = fmaxf(hi.x + bias[col + 2], 0.f);
            c.w = fmaxf(hi.y + bias[col + 3], 0.f);
            *reinterpret_cast<float4*>(&g_h2[(row + i) * 128 + col]) = c;
        }
    }
}

// ---------------- p = h2@W_a, q = h2@W_b ----------------
__global__ void k_pq(const float* __restrict__ we1) {
    __shared__ __align__(16) float As[16][64];
    __shared__ __align__(16) float Bs1[16][64];
    __shared__ __align__(16) float Bs2[16][64];
    int t = threadIdx.x;
    int row0 = blockIdx.x * 64;
    int col0 = blockIdx.y * 64;
    int lnode = t >> 2;
    int lk4   = (t & 3) * 4;
    int lkB   = t >> 4;
    int ljB   = (t & 15) * 4;
    int tx = t & 15, ty = t >> 4;
    unsigned long long acc1[4][2] = {};
    unsigned long long acc2[4][2] = {};

    for (int k0 = 0; k0 < 128; k0 += 16) {
        int row = row0 + lnode;
        float4 a;
        if (row < N_NODES)
            a = *reinterpret_cast<const float4*>(&g_h2[row * 128 + k0 + lk4]);
        else
            a = make_float4(0.f, 0.f, 0.f, 0.f);
        As[lk4 + 0][lnode] = a.x; As[lk4 + 1][lnode] = a.y;
        As[lk4 + 2][lnode] = a.z; As[lk4 + 3][lnode] = a.w;
        *reinterpret_cast<float4*>(&Bs1[lkB][ljB]) =
            *reinterpret_cast<const float4*>(&we1[(k0 + lkB) * 128 + col0 + ljB]);
        *reinterpret_cast<float4*>(&Bs2[lkB][ljB]) =
            *reinterpret_cast<const float4*>(&we1[(128 + k0 + lkB) * 128 + col0 + ljB]);
        __syncthreads();
#pragma unroll
        for (int kk = 0; kk < 16; kk++) {
            float4 av  = *reinterpret_cast<float4*>(&As[kk][ty * 4]);
            ulonglong2 b1v = *reinterpret_cast<ulonglong2*>(&Bs1[kk][tx * 4]);
            ulonglong2 b2v = *reinterpret_cast<ulonglong2*>(&Bs2[kk][tx * 4]);
            unsigned long long ad[4] = {dup2(av.x), dup2(av.y), dup2(av.z), dup2(av.w)};
#pragma unroll
            for (int i = 0; i < 4; i++) {
                fma2(acc1[i][0], ad[i], b1v.x);
                fma2(acc1[i][1], ad[i], b1v.y);
                fma2(acc2[i][0], ad[i], b2v.x);
                fma2(acc2[i][1], ad[i], b2v.y);
            }
        }
        __syncthreads();
    }

    int row = row0 + ty * 4;
    int col = col0 + tx * 4;
#pragma unroll
    for (int i = 0; i < 4; i++) {
        if (row + i < N_NODES) {
            float2 p0 = unpk2(acc1[i][0]), p1 = unpk2(acc1[i][1]);
            float2 q0 = unpk2(acc2[i][0]), q1 = unpk2(acc2[i][1]);
            *reinterpret_cast<float4*>(&g_p[(row + i) * 128 + col]) =
                make_float4(p0.x, p0.y, p1.x, p1.y);
            *reinterpret_cast<float4*>(&g_q[(row + i) * 128 + col]) =
                make_float4(q0.x, q0.y, q1.x, q1.y);
        }
    }
}

// ================= edge MLP via warp HMMA (bf16 2-term split, smem B) =========
// D[128x64] = Ahi*Bhi + Ahi*Blo + Alo*Bhi via mma.sync m16n8k16, fp32 acc.
// A (split e1) AND W2T (split) in padded smem; B fragments via ldmatrix.
// 2 CTAs/SM for phase overlap.
#define AROW 136                      // padded row (bf16 elems); 272 B
#define SM_A_HI   0                   // 128*272 = 34816 B
#define SM_A_LO   34816               // 34816 B
#define SM_B_HI   69632               // 64*272 = 17408 B  (W2T hi)
#define SM_B_LO   87040               // 17408 B           (W2T lo)
#define SM_OUTACC 104448              // float[128]
#define SM_B1S    104960              // float[128]
#define SM_WCS    105472              // float[512]
#define SM_B2S    107520              // float[64]
#define SM_W3S    107776              // float[64]
#define SM_EAS    108032              // float[512]
#define SM_SRC    110080              // int[128]
#define SM_DST    110592              // int[128]
#define SM_EDGE_TOTAL 111104

#define N_TILES (N_EDGES / 128)

__global__ __launch_bounds__(256, 2)
void k_edge_mma(const int* __restrict__ ei, const float* __restrict__ ea,
                const float* __restrict__ we1, const float* __restrict__ be1,
                const float* __restrict__ we2, const float* __restrict__ be2,
                const float* __restrict__ we3, const float* __restrict__ be3,
                float* __restrict__ out) {
    extern __shared__ __align__(16) char smem[];
    uint32_t smem_base = smem_u32(smem);
    int t = threadIdx.x;
    int wid = t >> 5, lane = t & 31;
    int wm = wid >> 1;            // warp M tile: rows wm*32..+31
    int wn = wid & 1;             // warp N half: cols wn*32..+31

    float* out_acc = (float*)(smem + SM_OUTACC);
    float* b1s = (float*)(smem + SM_B1S);
    float* wcs = (float*)(smem + SM_WCS);
    float* b2s = (float*)(smem + SM_B2S);
    float* w3s = (float*)(smem + SM_W3S);
    float* eas = (float*)(smem + SM_EAS);
    int*   srcs = (int*)(smem + SM_SRC);
    int*   dsts = (int*)(smem + SM_DST);

    if (t < 128) b1s[t] = be1[t];
    for (int i = t; i < 512; i += 256) wcs[i] = we1[256 * 128 + i];
    if (t < 64) { b2s[t] = be2[t]; w3s[t] = we3[t]; }

    // ---- stage W2T hi/lo into smem: BT[n][k] = we2[k*64+n], padded rows ----
    for (int idx = t; idx < 64 * 128; idx += 256) {
        int n = idx >> 7, k = idx & 127;
        float w = we2[k * 64 + n];
        float h = __bfloat162float(__float2bfloat16(w));
        uint32_t off = (uint32_t)n * (AROW * 2) + (uint32_t)k * 2;
        *(__nv_bfloat16*)(smem + SM_B_HI + off) = __float2bfloat16(h);
        *(__nv_bfloat16*)(smem + SM_B_LO + off) = __float2bfloat16(w - h);
    }
    float be3v = be3[0];

    // ldmatrix source coords
    int lrow = (lane & 7) + ((lane & 8) ? 8 : 0);      // A row-in-16
    int lcol = (lane & 16) ? 8 : 0;                    // A k-half
    // B (via BT rows): m0 = n 0-7/k0, m1 = n 0-7/k8, m2 = n 8-15/k0, m3 = n 8-15/k8
    int b_nrow = wn * 32 + ((lane >> 4) << 3) + (lane & 7);
    int b_khalf = (lane >> 3) & 1;
    uint32_t b_base = (uint32_t)b_nrow * (AROW * 2) + (uint32_t)b_khalf * 16;
    __syncthreads();

    for (int tile = blockIdx.x; tile < N_TILES; tile += gridDim.x) {
        int e0 = tile * 128;
        if (t < 128) { srcs[t] = ei[e0 + t]; out_acc[t] = 0.f; }
        else         { dsts[t - 128] = ei[N_EDGES + e0 + (t - 128)]; }
        for (int i = t; i < 512; i += 256) eas[i] = ea[e0 * 4 + i];
        __syncthreads();

        // ---- gather (float4, warp-per-edge) + e1 + bf16 split into smem A ----
#pragma unroll 4
        for (int i = 0; i < 16; i++) {
            int u = i * 256 + t;
            int edge = u >> 5;
            int k = (u & 31) * 4;
            int s = srcs[edge], d = dsts[edge];
            float4 pv = *reinterpret_cast<const float4*>(&g_p[s * 128 + k]);
            float4 qv = *reinterpret_cast<const float4*>(&g_q[d * 128 + k]);
            const float* eap = &eas[edge * 4];
            float e0a = eap[0], e1a = eap[1], e2a = eap[2], e3a = eap[3];
            float v[4];
            v[0] = pv.x + qv.x; v[1] = pv.y + qv.y;
            v[2] = pv.z + qv.z; v[3] = pv.w + qv.w;
            float hv[4];
#pragma unroll
            for (int j = 0; j < 4; j++) {
                float vv = v[j] + b1s[k + j]
                         + e0a * wcs[k + j]       + e1a * wcs[128 + k + j]
                         + e2a * wcs[256 + k + j] + e3a * wcs[384 + k + j];
                vv = fmaxf(vv, 0.f);
                v[j] = vv;
                hv[j] = __bfloat162float(__float2bfloat16(vv));
            }
            uint2 hp, lp;
            hp.x = pack_bf16(hv[0], hv[1]); hp.y = pack_bf16(hv[2], hv[3]);
            lp.x = pack_bf16(v[0] - hv[0], v[1] - hv[1]);
            lp.y = pack_bf16(v[2] - hv[2], v[3] - hv[3]);
            uint32_t off = (uint32_t)edge * (AROW * 2) + (uint32_t)k * 2;
            *(uint2*)(smem + SM_A_HI + off) = hp;
            *(uint2*)(smem + SM_A_LO + off) = lp;
        }
        __syncthreads();

        // ---- HMMA mainloop: warp tile 32(M)x32(N), K=128 ----
        float acc[2][4][4];
#pragma unroll
        for (int mi = 0; mi < 2; mi++)
#pragma unroll
            for (int nn = 0; nn < 4; nn++)
#pragma unroll
                for (int r = 0; r < 4; r++) acc[mi][nn][r] = 0.f;

#pragma unroll
        for (int kk = 0; kk < 8; kk++) {
            uint32_t ahi[2][4], alo[2][4];
            uint32_t aoff = (uint32_t)(wm * 32 + lrow) * (AROW * 2)
                          + (uint32_t)(kk * 16 + lcol) * 2;
            ldsm4(ahi[0], smem_base + SM_A_HI + aoff);
            ldsm4(ahi[1], smem_base + SM_A_HI + aoff + 16 * (AROW * 2));
            ldsm4(alo[0], smem_base + SM_A_LO + aoff);
            ldsm4(alo[1], smem_base + SM_A_LO + aoff + 16 * (AROW * 2));

            uint32_t bh01[4], bh23[4], bl01[4], bl23[4];
            uint32_t boff = b_base + (uint32_t)kk * 32;
            ldsm4(bh01, smem_base + SM_B_HI + boff);
            ldsm4(bh23, smem_base + SM_B_HI + boff + 16 * (AROW * 2));
            ldsm4(bl01, smem_base + SM_B_LO + boff);
            ldsm4(bl23, smem_base + SM_B_LO + boff + 16 * (AROW * 2));
            uint32_t* bh[4] = {bh01, bh01 + 2, bh23, bh23 + 2};
            uint32_t* bl[4] = {bl01, bl01 + 2, bl23, bl23 + 2};

#pragma unroll
            for (int mi = 0; mi < 2; mi++) {
#pragma unroll
                for (int nn = 0; nn < 4; nn++) {
                    mma16816(acc[mi][nn], ahi[mi], bh[nn]);
                    mma16816(acc[mi][nn], ahi[mi], bl[nn]);
                    mma16816(acc[mi][nn], alo[mi], bh[nn]);
                }
            }
        }

        // ---- epilogue: relu(D+b2)*w3, reduce over N ----
        float part[2][2] = {{0.f, 0.f}, {0.f, 0.f}};
#pragma unroll
        for (int mi = 0; mi < 2; mi++) {
#pragma unroll
            for (int nn = 0; nn < 4; nn++) {
                int c0 = wn * 32 + nn * 8 + (lane & 3) * 2;
                float w30 = w3s[c0], w31 = w3s[c0 + 1];
                float bb0 = b2s[c0], bb1 = b2s[c0 + 1];
                part[mi][0] += fmaxf(acc[mi][nn][0] + bb0, 0.f) * w30
                             + fmaxf(acc[mi][nn][1] + bb1, 0.f) * w31;
                part[mi][1] += fmaxf(acc[mi][nn][2] + bb0, 0.f) * w30
                             + fmaxf(acc[mi][nn][3] + bb1, 0.f) * w31;
            }
        }
#pragma unroll
        for (int mi = 0; mi < 2; mi++) {
#pragma unroll
            for (int g = 0; g < 2; g++) {
                part[mi][g] += __shfl_xor_sync(0xffffffffu, part[mi][g], 1);
                part[mi][g] += __shfl_xor_sync(0xffffffffu, part[mi][g], 2);
            }
        }
        if ((lane & 3) == 0) {
            int row = wm * 32 + (lane >> 2);
            atomicAdd(&out_acc[row],      part[0][0]);
            atomicAdd(&out_acc[row + 8],  part[0][1]);
            atomicAdd(&out_acc[row + 16], part[1][0]);
            atomicAdd(&out_acc[row + 24], part[1][1]);
        }
        __syncthreads();
        if (t < 128) out[e0 + t] = out_acc[t] + be3v;
        __syncthreads();
    }
}

// ---------------- launch ----------------
extern "C" void kernel_launch(void* const* d_in, const int* in_sizes, int n_in,
                              void* d_out, int out_size) {
    const float* x   = (const float*)d_in[0];
    const int*   ei  = (const int*)d_in[1];
    const float* ea  = (const float*)d_in[2];
    const float* w1r = (const float*)d_in[3];
    const float* w1n = (const float*)d_in[4];
    const float* b1  = (const float*)d_in[5];
    const float* w2r = (const float*)d_in[6];
    const float* w2n = (const float*)d_in[7];
    const float* b2  = (const float*)d_in[8];
    const float* we1 = (const float*)d_in[9];
    const float* be1 = (const float*)d_in[10];
    const float* we2 = (const float*)d_in[11];
    const float* be2 = (const float*)d_in[12];
    const float* we3 = (const float*)d_in[13];
    const float* be3 = (const float*)d_in[14];
    float* out = (float*)d_out;

    cudaFuncSetAttribute(k_edge_mma, cudaFuncAttributeMaxDynamicSharedMemorySize,
                         SM_EDGE_TOTAL);

    k_zero<<<12500, 256>>>();
    k_agg1<<<N_EDGES / 256, 256>>>(x, ei);
    k_h1<<<N_NODES / 2, 256>>>(x, w1r, w1n, b1);
    k_agg2<<<N_EDGES / 8, 256>>>(ei);
    k_h2<<<dim3((N_NODES + 63) / 64, 2), 256>>>(w2r, w2n, b2);
    k_pq<<<dim3((N_NODES + 63) / 64, 2), 256>>>(we1);
    k_edge_mma<<<296, 256, SM_EDGE_TOTAL>>>(ei, ea, we1, be1, we2, be2, we3, be3, out);
}

// round 8
// speedup vs baseline: 1.7712x; 1.0240x over previous
#include <cuda_runtime.h>
#include <cuda_bf16.h>
#include <cstdint>

#define N_NODES 100000
#define N_EDGES 1600000
#define HID 128

// ---------------- scratch (device globals; no allocation) ----------------
__device__ float g_cnt [N_NODES];
__device__ float g_agg1[N_NODES * 6];
__device__ float g_h1  [N_NODES * HID];
__device__ float g_agg2[N_NODES * HID];
__device__ float g_h2  [N_NODES * HID];
__device__ float g_p   [N_NODES * HID];   // h2 @ W_e1[0:128]
__device__ float g_q   [N_NODES * HID];   // h2 @ W_e1[128:256]

// ---------------- packed fp32x2 helpers ----------------
__device__ __forceinline__ void fma2(unsigned long long& acc,
                                     unsigned long long a, unsigned long long b) {
    asm("fma.rn.f32x2 %0, %1, %2, %0;" : "+l"(acc) : "l"(a), "l"(b));
}
__device__ __forceinline__ unsigned long long dup2(float x) {
    unsigned long long r;
    unsigned int u = __float_as_uint(x);
    asm("mov.b64 %0, {%1, %1};" : "=l"(r) : "r"(u));
    return r;
}
__device__ __forceinline__ float2 unpk2(unsigned long long v) {
    float2 f;
    asm("mov.b64 {%0, %1}, %2;" : "=f"(f.x), "=f"(f.y) : "l"(v));
    return f;
}

// ---------------- warp MMA helpers (baseline PTX) ----------------
__device__ __forceinline__ uint32_t smem_u32(const void* p) {
    uint32_t a;
    asm("{ .reg .u64 t; cvta.to.shared.u64 t, %1; cvt.u32.u64 %0, t; }" : "=r"(a) : "l"(p));
    return a;
}
__device__ __forceinline__ void mma16816(float* d, const uint32_t* a, const uint32_t* b) {
    asm volatile(
        "mma.sync.aligned.m16n8k16.row.col.f32.bf16.bf16.f32 "
        "{%0,%1,%2,%3}, {%4,%5,%6,%7}, {%8,%9}, {%0,%1,%2,%3};"
        : "+f"(d[0]), "+f"(d[1]), "+f"(d[2]), "+f"(d[3])
        : "r"(a[0]), "r"(a[1]), "r"(a[2]), "r"(a[3]), "r"(b[0]), "r"(b[1]));
}
__device__ __forceinline__ void ldsm4(uint32_t* r, uint32_t addr) {
    asm volatile("ldmatrix.sync.aligned.m8n8.x4.shared.b16 {%0,%1,%2,%3}, [%4];"
                 : "=r"(r[0]), "=r"(r[1]), "=r"(r[2]), "=r"(r[3]) : "r"(addr));
}
__device__ __forceinline__ uint32_t pack_bf16(float x, float y) {
    __nv_bfloat16 bx = __float2bfloat16(x), by = __float2bfloat16(y);
    return ((uint32_t)__bfloat16_as_ushort(by) << 16) | __bfloat16_as_ushort(bx);
}

// ---------------- zero scratch accumulators ----------------
__global__ void k_zero() {
    int i = blockIdx.x * 256 + threadIdx.x;
    float4 z = make_float4(0.f, 0.f, 0.f, 0.f);
    if (i < N_NODES * HID / 4) reinterpret_cast<float4*>(g_agg2)[i] = z;
    if (i < N_NODES * 6 / 4)   reinterpret_cast<float4*>(g_agg1)[i] = z;
    if (i < N_NODES / 4)       reinterpret_cast<float4*>(g_cnt)[i]  = z;
}

// ---------------- SAGE layer 1 scatter ----------------
__global__ void k_agg1(const float* __restrict__ x, const int* __restrict__ ei) {
    int e = blockIdx.x * 256 + threadIdx.x;
    int s = ei[e];
    int d = ei[N_EDGES + e];
    atomicAdd(&g_cnt[d], 1.0f);
    const float2* xr = reinterpret_cast<const float2*>(x + s * 6);
    float* dst = &g_agg1[d * 6];
#pragma unroll
    for (int k = 0; k < 3; k++) {
        float2 v = xr[k];
        asm volatile("red.global.add.v2.f32 [%0], {%1, %2};"
                     :: "l"(dst + k * 2), "f"(v.x), "f"(v.y) : "memory");
    }
}

// ---------------- h1 = relu(x@W1r + mean1@W1n + b1) ----------------
__global__ void k_h1(const float* __restrict__ x,
                     const float* __restrict__ w1r, const float* __restrict__ w1n,
                     const float* __restrict__ b1) {
    int t = threadIdx.x;
    int node = blockIdx.x * 2 + (t >> 7);
    int j = t & 127;
    float inv = 1.0f / fmaxf(g_cnt[node], 1.0f);
    float acc = b1[j];
#pragma unroll
    for (int k = 0; k < 6; k++) {
        acc += x[node * 6 + k] * w1r[k * 128 + j]
             + g_agg1[node * 6 + k] * inv * w1n[k * 128 + j];
    }
    g_h1[node * 128 + j] = fmaxf(acc, 0.f);
}

// ---------------- scatter h1[src] into agg2 (vector red) ----------------
__global__ void k_agg2(const int* __restrict__ ei) {
    int w = blockIdx.x * 8 + (threadIdx.x >> 5);
    int lane = threadIdx.x & 31;
    int s = ei[w];
    int d = ei[N_EDGES + w];
    float4 v = *reinterpret_cast<const float4*>(&g_h1[s * 128 + lane * 4]);
    float* dst = &g_agg2[d * 128 + lane * 4];
    asm volatile("red.global.add.v4.f32 [%0], {%1, %2, %3, %4};"
                 :: "l"(dst), "f"(v.x), "f"(v.y), "f"(v.z), "f"(v.w) : "memory");
}

// ---------------- h2 = relu(h1@W2r + mean2@W2n + b2), dual-A GEMM ----------------
__global__ void k_h2(const float* __restrict__ W1, const float* __restrict__ W2,
                     const float* __restrict__ bias) {
    __shared__ __align__(16) float As1[16][64];
    __shared__ __align__(16) float As2[16][64];
    __shared__ __align__(16) float Bs1[16][64];
    __shared__ __align__(16) float Bs2[16][64];
    int t = threadIdx.x;
    int row0 = blockIdx.x * 64;
    int col0 = blockIdx.y * 64;
    int lnode = t >> 2;
    int lk4   = (t & 3) * 4;
    int lkB   = t >> 4;
    int ljB   = (t & 15) * 4;
    int tx = t & 15, ty = t >> 4;
    unsigned long long acc[4][2] = {};

    for (int k0 = 0; k0 < 128; k0 += 16) {
        int row = row0 + lnode;
        float4 a1, a2;
        if (row < N_NODES) {
            a1 = *reinterpret_cast<const float4*>(&g_h1[row * 128 + k0 + lk4]);
            a2 = *reinterpret_cast<const float4*>(&g_agg2[row * 128 + k0 + lk4]);
            float inv = 1.0f / fmaxf(g_cnt[row], 1.0f);
            a2.x *= inv; a2.y *= inv; a2.z *= inv; a2.w *= inv;
        } else {
            a1 = a2 = make_float4(0.f, 0.f, 0.f, 0.f);
        }
        As1[lk4 + 0][lnode] = a1.x; As1[lk4 + 1][lnode] = a1.y;
        As1[lk4 + 2][lnode] = a1.z; As1[lk4 + 3][lnode] = a1.w;
        As2[lk4 + 0][lnode] = a2.x; As2[lk4 + 1][lnode] = a2.y;
        As2[lk4 + 2][lnode] = a2.z; As2[lk4 + 3][lnode] = a2.w;
        *reinterpret_cast<float4*>(&Bs1[lkB][ljB]) =
            *reinterpret_cast<const float4*>(&W1[(k0 + lkB) * 128 + col0 + ljB]);
        *reinterpret_cast<float4*>(&Bs2[lkB][ljB]) =
            *reinterpret_cast<const float4*>(&W2[(k0 + lkB) * 128 + col0 + ljB]);
        __syncthreads();
#pragma unroll
        for (int kk = 0; kk < 16; kk++) {
            float4 a1v = *reinterpret_cast<float4*>(&As1[kk][ty * 4]);
            float4 a2v = *reinterpret_cast<float4*>(&As2[kk][ty * 4]);
            ulonglong2 b1v = *reinterpret_cast<ulonglong2*>(&Bs1[kk][tx * 4]);
            ulonglong2 b2v = *reinterpret_cast<ulonglong2*>(&Bs2[kk][tx * 4]);
            unsigned long long a1d[4] = {dup2(a1v.x), dup2(a1v.y), dup2(a1v.z), dup2(a1v.w)};
            unsigned long long a2d[4] = {dup2(a2v.x), dup2(a2v.y), dup2(a2v.z), dup2(a2v.w)};
#pragma unroll
            for (int i = 0; i < 4; i++) {
                fma2(acc[i][0], a1d[i], b1v.x);
                fma2(acc[i][0], a2d[i], b2v.x);
                fma2(acc[i][1], a1d[i], b1v.y);
                fma2(acc[i][1], a2d[i], b2v.y);
            }
        }
        __syncthreads();
    }

    int row = row0 + ty * 4;
    int col = col0 + tx * 4;
#pragma unroll
    for (int i = 0; i < 4; i++) {
        if (row + i < N_NODES) {
            float2 lo = unpk2(acc[i][0]);
            float2 hi = unpk2(acc[i][1]);
            float4 c;
            c.x = fmaxf(lo.x + bias[col + 0], 0.f);
            c.y = fmaxf(lo.y + bias[col + 1], 0.f);
            c.z = fmaxf(hi.x + bias[col + 2], 0.f);
            c.w = fmaxf(hi.y + bias[col + 3], 0.f);
            *reinterpret_cast<float4*>(&g_h2[(row + i) * 128 + col]) = c;
        }
    }
}

// ---------------- p = h2@W_a, q = h2@W_b ----------------
__global__ void k_pq(const float* __restrict__ we1) {
    __shared__ __align__(16) float As[16][64];
    __shared__ __align__(16) float Bs1[16][64];
    __shared__ __align__(16) float Bs2[16][64];
    int t = threadIdx.x;
    int row0 = blockIdx.x * 64;
    int col0 = blockIdx.y * 64;
    int lnode = t >> 2;
    int lk4   = (t & 3) * 4;
    int lkB   = t >> 4;
    int ljB   = (t & 15) * 4;
    int tx = t & 15, ty = t >> 4;
    unsigned long long acc1[4][2] = {};
    unsigned long long acc2[4][2] = {};

    for (int k0 = 0; k0 < 128; k0 += 16) {
        int row = row0 + lnode;
        float4 a;
        if (row < N_NODES)
            a = *reinterpret_cast<const float4*>(&g_h2[row * 128 + k0 + lk4]);
        else
            a = make_float4(0.f, 0.f, 0.f, 0.f);
        As[lk4 + 0][lnode] = a.x; As[lk4 + 1][lnode] = a.y;
        As[lk4 + 2][lnode] = a.z; As[lk4 + 3][lnode] = a.w;
        *reinterpret_cast<float4*>(&Bs1[lkB][ljB]) =
            *reinterpret_cast<const float4*>(&we1[(k0 + lkB) * 128 + col0 + ljB]);
        *reinterpret_cast<float4*>(&Bs2[lkB][ljB]) =
            *reinterpret_cast<const float4*>(&we1[(128 + k0 + lkB) * 128 + col0 + ljB]);
        __syncthreads();
#pragma unroll
        for (int kk = 0; kk < 16; kk++) {
            float4 av  = *reinterpret_cast<float4*>(&As[kk][ty * 4]);
            ulonglong2 b1v = *reinterpret_cast<ulonglong2*>(&Bs1[kk][tx * 4]);
            ulonglong2 b2v = *reinterpret_cast<ulonglong2*>(&Bs2[kk][tx * 4]);
            unsigned long long ad[4] = {dup2(av.x), dup2(av.y), dup2(av.z), dup2(av.w)};
#pragma unroll
            for (int i = 0; i < 4; i++) {
                fma2(acc1[i][0], ad[i], b1v.x);
                fma2(acc1[i][1], ad[i], b1v.y);
                fma2(acc2[i][0], ad[i], b2v.x);
                fma2(acc2[i][1], ad[i], b2v.y);
            }
        }
        __syncthreads();
    }

    int row = row0 + ty * 4;
    int col = col0 + tx * 4;
#pragma unroll
    for (int i = 0; i < 4; i++) {
        if (row + i < N_NODES) {
            float2 p0 = unpk2(acc1[i][0]), p1 = unpk2(acc1[i][1]);
            float2 q0 = unpk2(acc2[i][0]), q1 = unpk2(acc2[i][1]);
            *reinterpret_cast<float4*>(&g_p[(row + i) * 128 + col]) =
                make_float4(p0.x, p0.y, p1.x, p1.y);
            *reinterpret_cast<float4*>(&g_q[(row + i) * 128 + col]) =
                make_float4(q0.x, q0.y, q1.x, q1.y);
        }
    }
}

// ================= edge MLP via warp HMMA (bf16 2-term split, smem B) =========
// D[128x64] = Ahi*Bhi + Ahi*Blo + Alo*Bhi via mma.sync m16n8k16, fp32 acc.
// MLP constants in registers; double-buffered idx/ea staging; 2 syncs/tile;
// atomic-free epilogue (per-N-half part arrays). 2 CTAs/SM.
#define AROW 136                      // padded row (bf16 elems); 272 B
#define SM_A_HI   0                   // 34816 B
#define SM_A_LO   34816               // 34816 B
#define SM_B_HI   69632               // 17408 B  (W2T hi)
#define SM_B_LO   87040               // 17408 B  (W2T lo)
#define SM_PA     104448              // float[128]
#define SM_PB     104960              // float[128]
#define SM_B2S    105472              // float[64]
#define SM_W3S    105728              // float[64]
#define SM_SRC    105984              // int[2][128]
#define SM_DST    107008              // int[2][128]
#define SM_EAS    108032              // float[2][512]
#define SM_EDGE_TOTAL 112128

#define N_TILES (N_EDGES / 128)
#define EDGE_GRID 296

__global__ __launch_bounds__(256, 2)
void k_edge_mma(const int* __restrict__ ei, const float* __restrict__ ea,
                const float* __restrict__ we1, const float* __restrict__ be1,
                const float* __restrict__ we2, const float* __restrict__ be2,
                const float* __restrict__ we3, const float* __restrict__ be3,
                float* __restrict__ out) {
    extern __shared__ __align__(16) char smem[];
    uint32_t smem_base = smem_u32(smem);
    int t = threadIdx.x;
    int wid = t >> 5, lane = t & 31;
    int wm = wid >> 1;            // warp M tile: rows wm*32..+31
    int wn = wid & 1;             // warp N half: cols wn*32..+31

    float* pa  = (float*)(smem + SM_PA);
    float* pb  = (float*)(smem + SM_PB);
    float* b2s = (float*)(smem + SM_B2S);
    float* w3s = (float*)(smem + SM_W3S);
    int*   srcs = (int*)(smem + SM_SRC);     // [2][128]
    int*   dsts = (int*)(smem + SM_DST);     // [2][128]
    float* eas  = (float*)(smem + SM_EAS);   // [2][512]

    if (t < 64) { b2s[t] = be2[t]; w3s[t] = we3[t]; }

    // ---- per-thread MLP constants (k fixed per lane) ----
    int kq = (lane) * 4;                     // this thread's k-quad
    float4 b1v = *reinterpret_cast<const float4*>(&be1[kq]);
    float4 wc0 = *reinterpret_cast<const float4*>(&we1[256 * 128 + kq]);
    float4 wc1 = *reinterpret_cast<const float4*>(&we1[257 * 128 + kq]);
    float4 wc2 = *reinterpret_cast<const float4*>(&we1[258 * 128 + kq]);
    float4 wc3 = *reinterpret_cast<const float4*>(&we1[259 * 128 + kq]);

    // ---- stage W2T hi/lo into smem: BT[n][k] = we2[k*64+n], padded rows ----
    for (int idx = t; idx < 64 * 128; idx += 256) {
        int n = idx >> 7, k = idx & 127;
        float w = we2[k * 64 + n];
        float h = __bfloat162float(__float2bfloat16(w));
        uint32_t off = (uint32_t)n * (AROW * 2) + (uint32_t)k * 2;
        *(__nv_bfloat16*)(smem + SM_B_HI + off) = __float2bfloat16(h);
        *(__nv_bfloat16*)(smem + SM_B_LO + off) = __float2bfloat16(w - h);
    }
    float be3v = be3[0];

    // ldmatrix source coords
    int lrow = (lane & 7) + ((lane & 8) ? 8 : 0);      // A row-in-16
    int lcol = (lane & 16) ? 8 : 0;                    // A k-half
    int b_nrow = wn * 32 + ((lane >> 4) << 3) + (lane & 7);
    int b_khalf = (lane >> 3) & 1;
    uint32_t b_base = (uint32_t)b_nrow * (AROW * 2) + (uint32_t)b_khalf * 16;

    // ---- prologue: stage tile 0 into buffer 0 ----
    int tile = blockIdx.x;
    {
        int e0 = tile * 128;
        if (t < 128) srcs[t] = ei[e0 + t];
        else         dsts[t - 128] = ei[N_EDGES + e0 + (t - 128)];
        for (int i = t; i < 512; i += 256) eas[i] = ea[e0 * 4 + i];
    }
    __syncthreads();

    int buf = 0;
    for (; tile < N_TILES; tile += EDGE_GRID) {
        int e0 = tile * 128;
        int* sb = srcs + buf * 128;
        int* db = dsts + buf * 128;
        float* eb = eas + buf * 512;

        // ---- gather (float4, warp-per-edge) + e1 + bf16 split into smem A ----
#pragma unroll 4
        for (int i = 0; i < 16; i++) {
            int edge = i * 8 + wid;
            int s = sb[edge], d = db[edge];
            float4 pv = *reinterpret_cast<const float4*>(&g_p[s * 128 + kq]);
            float4 qv = *reinterpret_cast<const float4*>(&g_q[d * 128 + kq]);
            float4 e4 = *reinterpret_cast<const float4*>(&eb[edge * 4]);
            float v[4], hv[4];
            v[0] = pv.x + qv.x + b1v.x + e4.x * wc0.x + e4.y * wc1.x + e4.z * wc2.x + e4.w * wc3.x;
            v[1] = pv.y + qv.y + b1v.y + e4.x * wc0.y + e4.y * wc1.y + e4.z * wc2.y + e4.w * wc3.y;
            v[2] = pv.z + qv.z + b1v.z + e4.x * wc0.z + e4.y * wc1.z + e4.z * wc2.z + e4.w * wc3.z;
            v[3] = pv.w + qv.w + b1v.w + e4.x * wc0.w + e4.y * wc1.w + e4.z * wc2.w + e4.w * wc3.w;
#pragma unroll
            for (int j = 0; j < 4; j++) {
                v[j] = fmaxf(v[j], 0.f);
                hv[j] = __bfloat162float(__float2bfloat16(v[j]));
            }
            uint2 hp, lp;
            hp.x = pack_bf16(hv[0], hv[1]); hp.y = pack_bf16(hv[2], hv[3]);
            lp.x = pack_bf16(v[0] - hv[0], v[1] - hv[1]);
            lp.y = pack_bf16(v[2] - hv[2], v[3] - hv[3]);
            uint32_t off = (uint32_t)edge * (AROW * 2) + (uint32_t)kq * 2;
            *(uint2*)(smem + SM_A_HI + off) = hp;
            *(uint2*)(smem + SM_A_LO + off) = lp;
        }

        // ---- stage next tile into other buffer (overlaps with gather) ----
        int nxt = tile + EDGE_GRID;
        if (nxt < N_TILES) {
            int e0n = nxt * 128;
            int* sn = srcs + (buf ^ 1) * 128;
            int* dn = dsts + (buf ^ 1) * 128;
            float* en = eas + (buf ^ 1) * 512;
            if (t < 128) sn[t] = ei[e0n + t];
            else         dn[t - 128] = ei[N_EDGES + e0n + (t - 128)];
            for (int i = t; i < 512; i += 256) en[i] = ea[e0n * 4 + i];
        }
        __syncthreads();

        // ---- HMMA mainloop: warp tile 32(M)x32(N), K=128 ----
        float acc[2][4][4];
#pragma unroll
        for (int mi = 0; mi < 2; mi++)
#pragma unroll
            for (int nn = 0; nn < 4; nn++)
#pragma unroll
                for (int r = 0; r < 4; r++) acc[mi][nn][r] = 0.f;

#pragma unroll
        for (int kk = 0; kk < 8; kk++) {
            uint32_t ahi[2][4], alo[2][4];
            uint32_t aoff = (uint32_t)(wm * 32 + lrow) * (AROW * 2)
                          + (uint32_t)(kk * 16 + lcol) * 2;
            ldsm4(ahi[0], smem_base + SM_A_HI + aoff);
            ldsm4(ahi[1], smem_base + SM_A_HI + aoff + 16 * (AROW * 2));
            ldsm4(alo[0], smem_base + SM_A_LO + aoff);
            ldsm4(alo[1], smem_base + SM_A_LO + aoff + 16 * (AROW * 2));

            uint32_t bh01[4], bh23[4], bl01[4], bl23[4];
            uint32_t boff = b_base + (uint32_t)kk * 32;
            ldsm4(bh01, smem_base + SM_B_HI + boff);
            ldsm4(bh23, smem_base + SM_B_HI + boff + 16 * (AROW * 2));
            ldsm4(bl01, smem_base + SM_B_LO + boff);
            ldsm4(bl23, smem_base + SM_B_LO + boff + 16 * (AROW * 2));
            uint32_t* bh[4] = {bh01, bh01 + 2, bh23, bh23 + 2};
            uint32_t* bl[4] = {bl01, bl01 + 2, bl23, bl23 + 2};

#pragma unroll
            for (int mi = 0; mi < 2; mi++) {
#pragma unroll
                for (int nn = 0; nn < 4; nn++) {
                    mma16816(acc[mi][nn], ahi[mi], bh[nn]);
                    mma16816(acc[mi][nn], ahi[mi], bl[nn]);
                    mma16816(acc[mi][nn], alo[mi], bh[nn]);
                }
            }
        }

        // ---- epilogue: relu(D+b2)*w3, reduce over N (atomic-free) ----
        float part[2][2] = {{0.f, 0.f}, {0.f, 0.f}};
#pragma unroll
        for (int mi = 0; mi < 2; mi++) {
#pragma unroll
            for (int nn = 0; nn < 4; nn++) {
                int c0 = wn * 32 + nn * 8 + (lane & 3) * 2;
                float w30 = w3s[c0], w31 = w3s[c0 + 1];
                float bb0 = b2s[c0], bb1 = b2s[c0 + 1];
                part[mi][0] += fmaxf(acc[mi][nn][0] + bb0, 0.f) * w30
                             + fmaxf(acc[mi][nn][1] + bb1, 0.f) * w31;
                part[mi][1] += fmaxf(acc[mi][nn][2] + bb0, 0.f) * w30
                             + fmaxf(acc[mi][nn][3] + bb1, 0.f) * w31;
            }
        }
#pragma unroll
        for (int mi = 0; mi < 2; mi++) {
#pragma unroll
            for (int g = 0; g < 2; g++) {
                part[mi][g] += __shfl_xor_sync(0xffffffffu, part[mi][g], 1);
                part[mi][g] += __shfl_xor_sync(0xffffffffu, part[mi][g], 2);
            }
        }
        if ((lane & 3) == 0) {
            float* pw = wn ? pb : pa;
            int r0 = wm * 32 + (lane >> 2);
            pw[r0]      = part[0][0];
            pw[r0 + 8]  = part[0][1];
            pw[r0 + 16] = part[1][0];
            pw[r0 + 24] = part[1][1];
        }
        __syncthreads();
        if (t < 128) out[e0 + t] = pa[t] + pb[t] + be3v;
        buf ^= 1;
    }
}

// ---------------- launch ----------------
extern "C" void kernel_launch(void* const* d_in, const int* in_sizes, int n_in,
                              void* d_out, int out_size) {
    const float* x   = (const float*)d_in[0];
    const int*   ei  = (const int*)d_in[1];
    const float* ea  = (const float*)d_in[2];
    const float* w1r = (const float*)d_in[3];
    const float* w1n = (const float*)d_in[4];
    const float* b1  = (const float*)d_in[5];
    const float* w2r = (const float*)d_in[6];
    const float* w2n = (const float*)d_in[7];
    const float* b2  = (const float*)d_in[8];
    const float* we1 = (const float*)d_in[9];
    const float* be1 = (const float*)d_in[10];
    const float* we2 = (const float*)d_in[11];
    const float* be2 = (const float*)d_in[12];
    const float* we3 = (const float*)d_in[13];
    const float* be3 = (const float*)d_in[14];
    float* out = (float*)d_out;

    cudaFuncSetAttribute(k_edge_mma, cudaFuncAttributeMaxDynamicSharedMemorySize,
                         SM_EDGE_TOTAL);

    k_zero<<<12500, 256>>>();
    k_agg1<<<N_EDGES / 256, 256>>>(x, ei);
    k_h1<<<N_NODES / 2, 256>>>(x, w1r, w1n, b1);
    k_agg2<<<N_EDGES / 8, 256>>>(ei);
    k_h2<<<dim3((N_NODES + 63) / 64, 2), 256>>>(w2r, w2n, b2);
    k_pq<<<dim3((N_NODES + 63) / 64, 2), 256>>>(we1);
    k_edge_mma<<<EDGE_GRID, 256, SM_EDGE_TOTAL>>>(ei, ea, we1, be1, we2, be2, we3, be3, out);
}